// round 9
// baseline (speedup 1.0000x reference)
#include <cuda_runtime.h>

// Beamform_1649267442279 — GB300 sm_103a — R9: R8 (streaming stores, best:
// 58.5us kernel, DRAM 82.7%) with 3 blocks/thread at third-channel spacing
// -> MLP_p1=12 front-batched LDG.64, three compact 1KB warp windows.
// __launch_bounds__(256, 2): reg ceiling 128 so ptxas neither clamps to 32
// (R6 failure: fake MLP) nor goes 1-CTA (R7 failure: occ 44%).
//
// Semantics: per channel s, blocks of 20 complex samples (40 floats).
// Block b, row r (0..3), col c (0..4):
//   re[r,c] = in_s[40b + 10r + 2c],  im[r,c] = in_s[40b + 10r + 2c + 1]
//   out[(s*Bc+b)*10 + c]     = sum_r br[r]*re - bi[r]*im
//   out[(s*Bc+b)*10 + 5 + c] = sum_r bi[r]*re + br[r]*im
// with br[r]=bf[2r], bi[r]=bf[2r+1].
// Bc = 500,000 is divisible by 3? No — 500000 = 3*166666 + 2. Handle the
// remainder blocks with tail threads mapped past third_blocks*5.

__device__ __forceinline__ void cmac4(float& re, float& im,
                                      const float4 w0, const float4 w1,
                                      const float2 v0, const float2 v1,
                                      const float2 v2, const float2 v3)
{
    re  = w0.x * v0.x - w0.y * v0.y;
    im  = w0.y * v0.x + w0.x * v0.y;
    re += w0.z * v1.x - w0.w * v1.y;
    im += w0.w * v1.x + w0.z * v1.y;
    re += w1.x * v2.x - w1.y * v2.y;
    im += w1.y * v2.x + w1.x * v2.y;
    re += w1.z * v3.x - w1.w * v3.y;
    im += w1.w * v3.x + w1.z * v3.y;
}

__global__ void __launch_bounds__(256, 2)
beamform_kernel(const float* __restrict__ in0,
                const float* __restrict__ in1,
                const float* __restrict__ in2,
                const float* __restrict__ in3,
                const float* __restrict__ bf,
                float* __restrict__ out,
                int third_blocks,      // floor(Bc / 3)
                int blocks_per_ch)     // Bc
{
    const int g = blockIdx.x * blockDim.x + threadIdx.x;

    const int ch = blockIdx.y;
    const float* __restrict__ in =
        (ch == 0) ? in0 : (ch == 1) ? in1 : (ch == 2) ? in2 : in3;

    // weights: uniform-address broadcast, L1-resident
    const float4 w0 = __ldg((const float4*)bf);      // br0, bi0, br1, bi1
    const float4 w1 = __ldg((const float4*)bf + 1);  // br2, bi2, br3, bi3

    const int n_main = third_blocks * 5;

    if (g < n_main) {
        const int b = g / 5;            // block within first third
        const int j = g - b * 5;        // column 0..4

        const size_t tstride = (size_t)third_blocks * 20;  // float2 per third

        // ---- front-batched loads: 12 independent LDG.64, 3 compact windows --
        const float2* __restrict__ pA =
            (const float2*)(in + (size_t)b * 40 + 2 * j);
        const float2* __restrict__ pB = pA + tstride;
        const float2* __restrict__ pC = pB + tstride;

        const float2 a0 = __ldg(pA + 0),  a1 = __ldg(pA + 5);
        const float2 a2 = __ldg(pA + 10), a3 = __ldg(pA + 15);
        const float2 b0 = __ldg(pB + 0),  b1 = __ldg(pB + 5);
        const float2 b2 = __ldg(pB + 10), b3 = __ldg(pB + 15);
        const float2 c0 = __ldg(pC + 0),  c1 = __ldg(pC + 5);
        const float2 c2 = __ldg(pC + 10), c3 = __ldg(pC + 15);

        float reA, imA, reB, imB, reC, imC;
        cmac4(reA, imA, w0, w1, a0, a1, a2, a3);
        cmac4(reB, imB, w0, w1, b0, b1, b2, b3);
        cmac4(reC, imC, w0, w1, c0, c1, c2, c3);

        const size_t ot = (size_t)third_blocks * 10;
        const size_t ob = ((size_t)ch * blocks_per_ch + (size_t)b) * 10;
        __stcs(out + ob + j,              reA);
        __stcs(out + ob + 5 + j,          imA);
        __stcs(out + ob + ot + j,         reB);
        __stcs(out + ob + ot + 5 + j,     imB);
        __stcs(out + ob + 2 * ot + j,     reC);
        __stcs(out + ob + 2 * ot + 5 + j, imC);
    } else {
        // ---- tail: blocks [3*third_blocks, Bc), one block per thread-slot --
        const int gt = g - n_main;
        const int n_tail = (blocks_per_ch - 3 * third_blocks) * 5;
        if (gt >= n_tail) return;

        const int bt = 3 * third_blocks + gt / 5;
        const int j  = gt % 5;

        const float2* __restrict__ p =
            (const float2*)(in + (size_t)bt * 40 + 2 * j);
        const float2 v0 = __ldg(p + 0);
        const float2 v1 = __ldg(p + 5);
        const float2 v2 = __ldg(p + 10);
        const float2 v3 = __ldg(p + 15);

        float re, im;
        cmac4(re, im, w0, w1, v0, v1, v2, v3);

        const size_t ob = ((size_t)ch * blocks_per_ch + (size_t)bt) * 10;
        __stcs(out + ob + j,     re);
        __stcs(out + ob + 5 + j, im);
    }
}

extern "C" void kernel_launch(void* const* d_in, const int* in_sizes, int n_in,
                              void* d_out, int out_size)
{
    const float* in0 = (const float*)d_in[0];
    const float* in1 = (const float*)d_in[1];
    const float* in2 = (const float*)d_in[2];
    const float* in3 = (const float*)d_in[3];
    const float* bf  = (const float*)d_in[4];
    float* out = (float*)d_out;

    const int N  = in_sizes[0];          // 20,000,000 floats / channel
    const int Bc = N / 40;               // 500,000 beam blocks per channel
    const int Tb = Bc / 3;               // 166,666 blocks per third

    const int threads = 256;
    const int tail_blocks = Bc - 3 * Tb; // 2
    const int n_thr = Tb * 5 + tail_blocks * 5;
    dim3 grid((n_thr + threads - 1) / threads, 4);

    beamform_kernel<<<grid, threads>>>(in0, in1, in2, in3, bf, out, Tb, Bc);
}